// round 2
// baseline (speedup 1.0000x reference)
#include <cuda_runtime.h>
#include <cuda_bf16.h>

// GraphNorm: per-graph segment normalization.
//   mean[b,d] = sum_{i in graph b} x[i,d] / cnt_b
//   sub       = x - mean[seg]*msc
//   var[b,d]  = sum sub^2 / cnt_b      (== E[x^2] - 2*m*s*m + (m*s)^2)
//   out       = gnw * sub / sqrt(var+eps) + gnb
//
// One CTA per (graph, 32-column chunk). The 512x32 fp32 slice (64 KB) lives in
// SMEM so x is read from HBM exactly once and written once: 256 MB total.
//
// NOTE: batch_num is int32 on device (JAX default x64-disabled downcasts the
// declared int64), confirmed by the R1 OOB crash when read as long long.

#define TILE_D     32
#define THREADS    512
#define ROW_TILE   512                  // max rows held in smem per CTA
#define NGROUPS    (THREADS / TILE_D)   // 16 row-groups for the reduction
#define TPR        (TILE_D / 4)         // 8 threads per row (float4)
#define ROWS_ITER  (THREADS / TPR)      // 64 rows per load iteration
#define EPSV       1e-6f

// dynamic smem: tile + 2 partial arrays + 2 coeff arrays
#define SMEM_BYTES ((ROW_TILE*TILE_D + 2*NGROUPS*TILE_D + 2*TILE_D) * sizeof(float))

__global__ __launch_bounds__(THREADS, 3)
void graphnorm_kernel(const float* __restrict__ x,
                      const float* __restrict__ gnw,
                      const float* __restrict__ gnb,
                      const float* __restrict__ msc,
                      const int* __restrict__ batch_num,
                      float* __restrict__ out,
                      int D)
{
    extern __shared__ float smem[];
    float* tile  = smem;                           // [ROW_TILE][TILE_D]
    float* ps1   = tile  + ROW_TILE * TILE_D;      // [NGROUPS][TILE_D]
    float* ps2   = ps1   + NGROUPS  * TILE_D;      // [NGROUPS][TILE_D]
    float* acoef = ps2   + NGROUPS  * TILE_D;      // [TILE_D]
    float* bcoef = acoef + TILE_D;                 // [TILE_D]

    const int g     = blockIdx.y;
    const int col0  = blockIdx.x * TILE_D;
    const int tid   = threadIdx.x;

    // node offset of this graph (B is small; trivial serial prefix)
    long long start = 0;
    for (int i = 0; i < g; ++i) start += (long long)batch_num[i];
    const int cnt = batch_num[g];

    const float* xg = x   + start * (long long)D + col0;
    float*       og = out + start * (long long)D + col0;

    const int lane_in_row = tid % TPR;        // which float4 within the 32 cols
    const int row_base    = tid / TPR;

    const int c   = tid % TILE_D;
    const int grp = tid / TILE_D;

    if (cnt <= ROW_TILE) {
        // ---------- fast path: slice resident in SMEM ----------
        for (int r = row_base; r < cnt; r += ROWS_ITER) {
            float4 v = *(const float4*)(xg + (long long)r * D + lane_in_row * 4);
            *(float4*)(tile + r * TILE_D + lane_in_row * 4) = v;
        }
        __syncthreads();

        float s1 = 0.f, s2 = 0.f;
        for (int r = grp; r < cnt; r += NGROUPS) {
            float v = tile[r * TILE_D + c];
            s1 += v;
            s2 += v * v;
        }
        ps1[grp * TILE_D + c] = s1;
        ps2[grp * TILE_D + c] = s2;
        __syncthreads();

        if (tid < TILE_D) {
            float t1 = 0.f, t2 = 0.f;
            #pragma unroll
            for (int k = 0; k < NGROUPS; ++k) {
                t1 += ps1[k * TILE_D + tid];
                t2 += ps2[k * TILE_D + tid];
            }
            const float inv_n = 1.0f / (float)cnt;
            const float m   = t1 * inv_n;
            const float ex2 = t2 * inv_n;
            const float s   = msc[col0 + tid];
            const float ms  = m * s;
            const float var = ex2 - 2.f * ms * m + ms * ms;
            const float rstd = rsqrtf(var + EPSV);
            const float a = gnw[col0 + tid] * rstd;
            acoef[tid] = a;
            bcoef[tid] = gnb[col0 + tid] - a * ms;
        }
        __syncthreads();

        const float4 av = *(const float4*)(acoef + lane_in_row * 4);
        const float4 bv = *(const float4*)(bcoef + lane_in_row * 4);
        for (int r = row_base; r < cnt; r += ROWS_ITER) {
            float4 v = *(const float4*)(tile + r * TILE_D + lane_in_row * 4);
            float4 o;
            o.x = fmaf(av.x, v.x, bv.x);
            o.y = fmaf(av.y, v.y, bv.y);
            o.z = fmaf(av.z, v.z, bv.z);
            o.w = fmaf(av.w, v.w, bv.w);
            *(float4*)(og + (long long)r * D + lane_in_row * 4) = o;
        }
    } else {
        // ---------- fallback: graph larger than tile; two global passes ----------
        float s1 = 0.f, s2 = 0.f;
        for (int r = grp; r < cnt; r += NGROUPS) {
            float v = xg[(long long)r * D + c];
            s1 += v;
            s2 += v * v;
        }
        ps1[grp * TILE_D + c] = s1;
        ps2[grp * TILE_D + c] = s2;
        __syncthreads();

        if (tid < TILE_D) {
            float t1 = 0.f, t2 = 0.f;
            #pragma unroll
            for (int k = 0; k < NGROUPS; ++k) {
                t1 += ps1[k * TILE_D + tid];
                t2 += ps2[k * TILE_D + tid];
            }
            const float inv_n = 1.0f / (float)cnt;
            const float m   = t1 * inv_n;
            const float ex2 = t2 * inv_n;
            const float s   = msc[col0 + tid];
            const float ms  = m * s;
            const float var = ex2 - 2.f * ms * m + ms * ms;
            const float rstd = rsqrtf(var + EPSV);
            const float a = gnw[col0 + tid] * rstd;
            acoef[tid] = a;
            bcoef[tid] = gnb[col0 + tid] - a * ms;
        }
        __syncthreads();

        const float4 av = *(const float4*)(acoef + lane_in_row * 4);
        const float4 bv = *(const float4*)(bcoef + lane_in_row * 4);
        for (int r = row_base; r < cnt; r += ROWS_ITER) {
            float4 v = *(const float4*)(xg + (long long)r * D + lane_in_row * 4);
            float4 o;
            o.x = fmaf(av.x, v.x, bv.x);
            o.y = fmaf(av.y, v.y, bv.y);
            o.z = fmaf(av.z, v.z, bv.z);
            o.w = fmaf(av.w, v.w, bv.w);
            *(float4*)(og + (long long)r * D + lane_in_row * 4) = o;
        }
    }
}

extern "C" void kernel_launch(void* const* d_in, const int* in_sizes, int n_in,
                              void* d_out, int out_size)
{
    const float* x   = (const float*)d_in[0];
    const float* gnw = (const float*)d_in[1];
    const float* gnb = (const float*)d_in[2];
    const float* msc = (const float*)d_in[3];
    const int*   bn  = (const int*)d_in[4];
    float* out = (float*)d_out;

    const int D = in_sizes[1];     // HIDDEN (gnw length)
    const int B = in_sizes[4];     // NUM_GRAPHS

    cudaFuncSetAttribute(graphnorm_kernel,
                         cudaFuncAttributeMaxDynamicSharedMemorySize,
                         (int)SMEM_BYTES);

    dim3 grid(D / TILE_D, B);
    graphnorm_kernel<<<grid, THREADS, SMEM_BYTES>>>(x, gnw, gnb, msc, bn, out, D);
}